// round 3
// baseline (speedup 1.0000x reference)
#include <cuda_runtime.h>

#define R_GAS   8.3144621f
#define F_CONST 96487.0f
#define ALPHA   0.5f
#define SN_C    0.000437545f
#define SP_C    0.00030962f
#define KN_C    2120.96f
#define KP_C    248898.0f
#define RO_C    0.117215f
#define T_O     6.08671f
#define T_SN    1001.38f
#define T_SP    46.4311f
#define U0P     4.03f
#define U0N     0.01f
#define Q_MAX   (7600.0f / 0.6f)
#define VOL     2e-05f
#define VOL_S   (0.1f * VOL)
#define VOL_B   (VOL - VOL_S)
#define Q_S_MAX (Q_MAX * VOL_S / VOL)

#define INV_QSMAX  (1.0f / Q_S_MAX)
#define INV_VOLB   (1.0f / VOL_B)
#define INV_VOLS   (1.0f / VOL_S)
#define T_DIFF_    7000000.0f
#define INV_TDIFF  (1.0f / T_DIFF_)
#define INV_TO     (1.0f / T_O)
#define INV_TSN    (1.0f / T_SN)
#define INV_TSP    (1.0f / T_SP)
#define INV_F      (1.0f / F_CONST)
#define RTF_C      (R_GAS / F_CONST)
#define RTFA_C     (R_GAS / F_CONST / ALPHA)
#define CN_C       (1.0f / (SN_C * 2.0f * KN_C))
#define CP_C       (1.0f / (SP_C * 2.0f * KP_C))
#define AN0_F      (86.19f / F_CONST)

__device__ __constant__ float AP_C[13] = {
    -31593.7f, 0.106747f, 24606.4f, -78561.9f, 13317.9f, 307387.0f,
    84916.1f, -1074690.0f, 2285.04f, 990894.0f, 283920.0f, -161513.0f, -469218.0f
};

__device__ __forceinline__ float ve_sum_p(float x) {
    float m  = 2.0f * x - 1.0f;
    float s  = AP_C[0] * m;
    float pw = 1.0f;
    float m2 = m * m;
    float tx = 2.0f * x * (1.0f - x);
#pragma unroll
    for (int k = 1; k < 13; ++k) {
        s  = fmaf(AP_C[k] * pw, fmaf(-tx, (float)k, m2), s);
        pw = pw * m;
    }
    return s * INV_F;
}

__device__ __forceinline__ float fast_asinh_pos(float y) {
    return __logf(y + sqrtf(fmaf(y, y, 1.0f)));
}

// Per-cell computation: state (a,b), input i -> (z0, z1, x_next[8])
__device__ __forceinline__ void cell_compute(float i, float4 a, float4 b,
                                             float2& z, float4& xo0, float4& xo1)
{
    float Tb = a.x, Vo = a.y, Vsn = a.z, Vsp = a.w;
    float qnB = b.x, qnS = b.y, qpB = b.z, qpS = b.w;

    float xnS = qnS * INV_QSMAX;
    float xpS = qpS * INV_QSMAX;

    float qdDn = (qnB * INV_VOLB - qnS * INV_VOLS) * INV_TDIFF;
    float qdDp = (qpB * INV_VOLB - qpS * INV_VOLS) * INV_TDIFF;

    float argN = i * CN_C * rsqrtf(xnS * (1.0f - xnS));
    float argP = i * CP_C * rsqrtf(xpS * (1.0f - xpS));

    float rtfa   = RTFA_C * Tb;
    float VsnNom = rtfa * fast_asinh_pos(argN);
    float VspNom = rtfa * fast_asinh_pos(argP);

    float Vo_n  = Vo  + (fmaf(i, RO_C, -Vo)) * INV_TO;
    float Vsn_n = Vsn + (VsnNom - Vsn) * INV_TSN;
    float Vsp_n = Vsp + (VspNom - Vsp) * INV_TSP;
    float qnB_n = qnB - qdDn;
    float qnS_n = qnS + (qdDn - i);
    float qpB_n = qpB - qdDp;
    float qpS_n = qpS + (i + qdDp);

    float xnS2 = qnS_n * INV_QSMAX;
    float xpS2 = qpS_n * INV_QSMAX;

    float rtf = RTF_C * Tb;
    float mN  = 2.0f * xnS2 - 1.0f;
    float Ven = U0N + rtf * __logf(__fdividef(1.0f - xnS2, xnS2)) + AN0_F * mN;
    float Vep = U0P + rtf * __logf(__fdividef(1.0f - xpS2, xpS2)) + ve_sum_p(xpS2);

    float V = Vep - Ven - Vo_n - Vsn_n - Vsp_n;

    z   = make_float2(Tb - 273.15f, V);
    xo0 = make_float4(Tb, Vo_n, Vsn_n, Vsp_n);
    xo1 = make_float4(qnB_n, qnS_n, qpB_n, qpS_n);
}

__global__ void __launch_bounds__(256)
battery_cell_kernel2(const float* __restrict__ inp,
                     const float* __restrict__ states,
                     float* __restrict__ out, int B)
{
    int t  = blockIdx.x * blockDim.x + threadIdx.x;
    int c0 = 2 * t;
    if (c0 >= B) return;

    // Front-batched loads: 1x float2 + 4x float4 (all coalesced, 16B-aligned)
    float2 ii = *reinterpret_cast<const float2*>(inp + c0);
    const float4* s4 = reinterpret_cast<const float4*>(states) + 2 * c0;
    float4 a0 = s4[0];
    float4 b0 = s4[1];
    float4 a1 = s4[2];
    float4 b1 = s4[3];

    float2 z0, z1;
    float4 x00, x01, x10, x11;
    cell_compute(ii.x, a0, b0, z0, x00, x01);
    cell_compute(ii.y, a1, b1, z1, x10, x11);

    // Z: two cells' float2 -> one float4 store
    float4 zz = make_float4(z0.x, z0.y, z1.x, z1.y);
    __stcs(reinterpret_cast<float4*>(out) + t, zz);

    float4* x4 = reinterpret_cast<float4*>(out + 2LL * B) + 2 * c0;
    __stcs(x4 + 0, x00);
    __stcs(x4 + 1, x01);
    __stcs(x4 + 2, x10);
    __stcs(x4 + 3, x11);
}

extern "C" void kernel_launch(void* const* d_in, const int* in_sizes, int n_in,
                              void* d_out, int out_size)
{
    const float* inp    = (const float*)d_in[0];   // (B,1)
    const float* states = (const float*)d_in[1];   // (B,8)
    int B = in_sizes[0];
    float* out = (float*)d_out;                    // Z (B,2) ++ X_next (B,8)

    int threads = 256;
    int cells_per_block = threads * 2;
    int blocks = (B + cells_per_block - 1) / cells_per_block;
    battery_cell_kernel2<<<blocks, threads>>>(inp, states, out, B);
}

// round 4
// speedup vs baseline: 1.0479x; 1.0479x over previous
#include <cuda_runtime.h>

#define R_GAS   8.3144621f
#define F_CONST 96487.0f
#define ALPHA   0.5f
#define SN_C    0.000437545f
#define SP_C    0.00030962f
#define KN_C    2120.96f
#define KP_C    248898.0f
#define RO_C    0.117215f
#define T_O     6.08671f
#define T_SN    1001.38f
#define T_SP    46.4311f
#define U0P     4.03f
#define U0N     0.01f
#define Q_MAX   (7600.0f / 0.6f)
#define VOL     2e-05f
#define VOL_S   (0.1f * VOL)
#define VOL_B   (VOL - VOL_S)
#define Q_S_MAX (Q_MAX * VOL_S / VOL)
#define LN2_F   0.69314718055994531f

#define INV_QSMAX  (1.0f / Q_S_MAX)
#define INV_VOLB   (1.0f / VOL_B)
#define INV_VOLS   (1.0f / VOL_S)
#define T_DIFF_    7000000.0f
#define INV_TDIFF  (1.0f / T_DIFF_)
#define INV_TO     (1.0f / T_O)
#define INV_TSN    (1.0f / T_SN)
#define INV_TSP    (1.0f / T_SP)
#define INV_F      (1.0f / F_CONST)
// ln-folded premultipliers: x * ln2 applied at compile time
#define RTF_LN2    (R_GAS / F_CONST * LN2_F)            // (R/F)*ln2
#define RTFA_LN2   (R_GAS / F_CONST / ALPHA * LN2_F)    // (R/F/alpha)*ln2
#define CN_C       (1.0f / (SN_C * 2.0f * KN_C))
#define CP_C       (1.0f / (SP_C * 2.0f * KP_C))
#define AN0_F      (86.19f / F_CONST)

__device__ __constant__ float AP_C[13] = {
    -31593.7f, 0.106747f, 24606.4f, -78561.9f, 13317.9f, 307387.0f,
    84916.1f, -1074690.0f, 2285.04f, 990894.0f, 283920.0f, -161513.0f, -469218.0f
};

__device__ __forceinline__ float ve_sum_p(float x) {
    float m  = 2.0f * x - 1.0f;
    float s  = AP_C[0] * m;
    float pw = 1.0f;
    float m2 = m * m;
    float tx = 2.0f * x * (1.0f - x);
#pragma unroll
    for (int k = 1; k < 13; ++k) {
        s  = fmaf(AP_C[k] * pw, fmaf(-tx, (float)k, m2), s);
        pw = pw * m;
    }
    return s * INV_F;
}

// log2(asinh arg) for y > 0: log2(y + sqrt(y^2+1)), sqrt via v*rsqrt(v)
__device__ __forceinline__ float asinh_log2_pos(float y) {
    float v = fmaf(y, y, 1.0f);     // v >= 1, rsqrt safe
    float s = v * rsqrtf(v);        // ~sqrt(v), 1 MUFU, no refinement
    return __log2f(y + s);
}

__global__ void __launch_bounds__(256)
battery_cell_kernel(const float* __restrict__ inp,
                    const float* __restrict__ states,
                    float* __restrict__ out, int B)
{
    int t = blockIdx.x * blockDim.x + threadIdx.x;
    if (t >= B) return;

    const float4* s4 = reinterpret_cast<const float4*>(states) + 2 * t;
    float4 a = s4[0];
    float4 b = s4[1];
    float Tb = a.x, Vo = a.y, Vsn = a.z, Vsp = a.w;
    float qnB = b.x, qnS = b.y, qpB = b.z, qpS = b.w;
    float i = inp[t];

    float xnS = qnS * INV_QSMAX;
    float xpS = qpS * INV_QSMAX;

    float qdDn = (qnB * INV_VOLB - qnS * INV_VOLS) * INV_TDIFF;
    float qdDp = (qpB * INV_VOLB - qpS * INV_VOLS) * INV_TDIFF;

    // asinh argument: i * C * rsqrt(x(1-x))
    float argN = i * CN_C * rsqrtf(xnS * (1.0f - xnS));
    float argP = i * CP_C * rsqrtf(xpS * (1.0f - xpS));

    float rtfa   = RTFA_LN2 * Tb;   // includes ln2 for log2->ln
    float VsnNom = rtfa * asinh_log2_pos(argN);
    float VspNom = rtfa * asinh_log2_pos(argP);

    float Vo_n  = Vo  + (fmaf(i, RO_C, -Vo)) * INV_TO;
    float Vsn_n = Vsn + (VsnNom - Vsn) * INV_TSN;
    float Vsp_n = Vsp + (VspNom - Vsp) * INV_TSP;
    float qnB_n = qnB - qdDn;
    float qnS_n = qnS + (qdDn - i);
    float qpB_n = qpB - qdDp;
    float qpS_n = qpS + (i + qdDp);

    float xnS2 = qnS_n * INV_QSMAX;
    float xpS2 = qpS_n * INV_QSMAX;

    float rtf = RTF_LN2 * Tb;       // includes ln2
    // ln((1-x)/x) = ln2*(log2(1-x) - log2(x)): two independent MUFU.LG2
    float lgN = __log2f(1.0f - xnS2) - __log2f(xnS2);
    float lgP = __log2f(1.0f - xpS2) - __log2f(xpS2);
    float mN  = 2.0f * xnS2 - 1.0f;
    float Ven = U0N + rtf * lgN + AN0_F * mN;
    float Vep = U0P + rtf * lgP + ve_sum_p(xpS2);

    float V = Vep - Ven - Vo_n - Vsn_n - Vsp_n;

    // Output: Z (B,2) then X_next (B,8)
    float2* z2 = reinterpret_cast<float2*>(out) + t;
    z2[0] = make_float2(Tb - 273.15f, V);

    float4* x4 = reinterpret_cast<float4*>(out + 2LL * B) + 2 * t;
    x4[0] = make_float4(Tb, Vo_n, Vsn_n, Vsp_n);
    x4[1] = make_float4(qnB_n, qnS_n, qpB_n, qpS_n);
}

extern "C" void kernel_launch(void* const* d_in, const int* in_sizes, int n_in,
                              void* d_out, int out_size)
{
    const float* inp    = (const float*)d_in[0];   // (B,1)
    const float* states = (const float*)d_in[1];   // (B,8)
    int B = in_sizes[0];
    float* out = (float*)d_out;                    // Z (B,2) ++ X_next (B,8)

    int threads = 256;
    int blocks = (B + threads - 1) / threads;
    battery_cell_kernel<<<blocks, threads>>>(inp, states, out, B);
}

// round 5
// speedup vs baseline: 1.0676x; 1.0188x over previous
#include <cuda_runtime.h>

#define R_GAS   8.3144621f
#define F_CONST 96487.0f
#define ALPHA   0.5f
#define SN_C    0.000437545f
#define SP_C    0.00030962f
#define KN_C    2120.96f
#define KP_C    248898.0f
#define RO_C    0.117215f
#define T_O     6.08671f
#define T_SN    1001.38f
#define T_SP    46.4311f
#define U0P     4.03f
#define U0N     0.01f
#define Q_MAX   (7600.0f / 0.6f)
#define VOL     2e-05f
#define VOL_S   (0.1f * VOL)
#define VOL_B   (VOL - VOL_S)
#define Q_S_MAX (Q_MAX * VOL_S / VOL)
#define LN2_F   0.69314718055994531f

#define INV_QSMAX  (1.0f / Q_S_MAX)
#define INV_VOLB   (1.0f / VOL_B)
#define INV_VOLS   (1.0f / VOL_S)
#define T_DIFF_    7000000.0f
#define INV_TDIFF  (1.0f / T_DIFF_)
#define INV_TO     (1.0f / T_O)
#define INV_TSN    (1.0f / T_SN)
#define INV_TSP    (1.0f / T_SP)
#define INV_F      (1.0f / F_CONST)
#define RTF_LN2    (R_GAS / F_CONST * LN2_F)
#define RTFA_LN2   (R_GAS / F_CONST / ALPHA * LN2_F)
#define CN_C       (1.0f / (SN_C * 2.0f * KN_C))
#define CP_C       (1.0f / (SP_C * 2.0f * KP_C))
#define AN0_F      (86.19f / F_CONST)

__device__ __constant__ float AP_C[13] = {
    -31593.7f, 0.106747f, 24606.4f, -78561.9f, 13317.9f, 307387.0f,
    84916.1f, -1074690.0f, 2285.04f, 990894.0f, 283920.0f, -161513.0f, -469218.0f
};

__device__ __forceinline__ float ve_sum_p(float x) {
    float m  = 2.0f * x - 1.0f;
    float s  = AP_C[0] * m;
    float pw = 1.0f;
    float m2 = m * m;
    float tx = 2.0f * x * (1.0f - x);
#pragma unroll
    for (int k = 1; k < 13; ++k) {
        s  = fmaf(AP_C[k] * pw, fmaf(-tx, (float)k, m2), s);
        pw = pw * m;
    }
    return s * INV_F;
}

// log2(y + sqrt(y^2+1)) for y > 0; sqrt via v*rsqrt(v), no refinement
__device__ __forceinline__ float asinh_log2_pos(float y) {
    float v = fmaf(y, y, 1.0f);
    float s = v * rsqrtf(v);
    return __log2f(y + s);
}

__global__ void __launch_bounds__(512)
battery_cell_kernel(const float* __restrict__ inp,
                    const float* __restrict__ states,
                    float* __restrict__ out, int B)
{
    int t = blockIdx.x * blockDim.x + threadIdx.x;
    if (t >= B) return;

    // Streaming reads: single-use data, evict-first
    float i = __ldcs(inp + t);
    const float4* s4 = reinterpret_cast<const float4*>(states) + 2 * t;
    float4 a = __ldcs(s4 + 0);
    float4 b = __ldcs(s4 + 1);
    float Tb = a.x, Vo = a.y, Vsn = a.z, Vsp = a.w;
    float qnB = b.x, qnS = b.y, qpB = b.z, qpS = b.w;

    float xnS = qnS * INV_QSMAX;
    float xpS = qpS * INV_QSMAX;

    float qdDn = (qnB * INV_VOLB - qnS * INV_VOLS) * INV_TDIFF;
    float qdDp = (qpB * INV_VOLB - qpS * INV_VOLS) * INV_TDIFF;

    float argN = i * CN_C * rsqrtf(xnS * (1.0f - xnS));
    float argP = i * CP_C * rsqrtf(xpS * (1.0f - xpS));

    float rtfa   = RTFA_LN2 * Tb;
    float VsnNom = rtfa * asinh_log2_pos(argN);
    float VspNom = rtfa * asinh_log2_pos(argP);

    float Vo_n  = Vo  + (fmaf(i, RO_C, -Vo)) * INV_TO;
    float Vsn_n = Vsn + (VsnNom - Vsn) * INV_TSN;
    float Vsp_n = Vsp + (VspNom - Vsp) * INV_TSP;
    float qnB_n = qnB - qdDn;
    float qnS_n = qnS + (qdDn - i);
    float qpB_n = qpB - qdDp;
    float qpS_n = qpS + (i + qdDp);

    float xnS2 = qnS_n * INV_QSMAX;
    float xpS2 = qpS_n * INV_QSMAX;

    float rtf = RTF_LN2 * Tb;
    float lgN = __log2f(1.0f - xnS2) - __log2f(xnS2);
    float lgP = __log2f(1.0f - xpS2) - __log2f(xpS2);
    float mN  = 2.0f * xnS2 - 1.0f;
    float Ven = U0N + rtf * lgN + AN0_F * mN;
    float Vep = U0P + rtf * lgP + ve_sum_p(xpS2);

    float V = Vep - Ven - Vo_n - Vsn_n - Vsp_n;

    // Streaming stores: output never re-read by this kernel
    __stcs(reinterpret_cast<float2*>(out) + t, make_float2(Tb - 273.15f, V));

    float4* x4 = reinterpret_cast<float4*>(out + 2LL * B) + 2 * t;
    __stcs(x4 + 0, make_float4(Tb, Vo_n, Vsn_n, Vsp_n));
    __stcs(x4 + 1, make_float4(qnB_n, qnS_n, qpB_n, qpS_n));
}

extern "C" void kernel_launch(void* const* d_in, const int* in_sizes, int n_in,
                              void* d_out, int out_size)
{
    const float* inp    = (const float*)d_in[0];   // (B,1)
    const float* states = (const float*)d_in[1];   // (B,8)
    int B = in_sizes[0];
    float* out = (float*)d_out;                    // Z (B,2) ++ X_next (B,8)

    int threads = 512;
    int blocks = (B + threads - 1) / threads;
    battery_cell_kernel<<<blocks, threads>>>(inp, states, out, B);
}